// round 15
// baseline (speedup 1.0000x reference)
#include <cuda_runtime.h>
#include <cuda_fp16.h>
#include <cstdint>

#define NB    32
#define CIN   64
#define COUT  128
#define HDIM  64
#define WDIM  64
#define EPSV  1e-8f
#define FM_OFF (NB * COUT * HDIM * WDIM)
#define NTILES 32768              // 32 n * 32 ty * 32 tx (2x2 output tiles)
#define LSC   2048.0f             // lo-plane scale 2^11
#define ILSC  4.8828125e-4f       // 2^-11

// ---- scratch (static __device__, no allocations) ----
__device__ float g_inv_norm[COUT];
// A operand (input transform), fp16 hi + scaled-lo: [pos][tile][ci]
__device__ __align__(128) __half g_Xh[16][NTILES][64];
__device__ __align__(128) __half g_Xl[16][NTILES][64];
// B operand (weight transform): [pos][ci][co]
__device__ __align__(128) __half g_Wh[16][64][128];
__device__ __align__(128) __half g_Wl[16][64][128];

// ---- helpers ----
__device__ __forceinline__ void cpa16(uint32_t dst, const void* src) {
    asm volatile("cp.async.ca.shared.global [%0], [%1], 16;" :: "r"(dst), "l"(src));
}
__device__ __forceinline__ void cpcommit() {
    asm volatile("cp.async.commit_group;" ::: "memory");
}
template <int N>
__device__ __forceinline__ void cpwait() {
    asm volatile("cp.async.wait_group %0;" :: "n"(N) : "memory");
}
__device__ __forceinline__ void ldsm_x4(uint32_t& r0, uint32_t& r1, uint32_t& r2,
                                        uint32_t& r3, uint32_t a) {
    asm volatile("ldmatrix.sync.aligned.m8n8.x4.shared.b16 {%0,%1,%2,%3}, [%4];"
                 : "=r"(r0), "=r"(r1), "=r"(r2), "=r"(r3) : "r"(a));
}
__device__ __forceinline__ void ldsm_x4t(uint32_t& r0, uint32_t& r1, uint32_t& r2,
                                         uint32_t& r3, uint32_t a) {
    asm volatile("ldmatrix.sync.aligned.m8n8.x4.trans.shared.b16 {%0,%1,%2,%3}, [%4];"
                 : "=r"(r0), "=r"(r1), "=r"(r2), "=r"(r3) : "r"(a));
}
__device__ __forceinline__ void mma16(float* d, const uint32_t* a, uint32_t b0,
                                      uint32_t b1) {
    asm volatile(
        "mma.sync.aligned.m16n8k16.row.col.f32.f16.f16.f32 "
        "{%0,%1,%2,%3},{%4,%5,%6,%7},{%8,%9},{%0,%1,%2,%3};"
        : "+f"(d[0]), "+f"(d[1]), "+f"(d[2]), "+f"(d[3])
        : "r"(a[0]), "r"(a[1]), "r"(a[2]), "r"(a[3]), "r"(b0), "r"(b1));
}
__device__ __forceinline__ void hsplit(float v, uint16_t& h, uint16_t& l) {
    __half hb = __float2half(v);
    __half lb = __float2half((v - __half2float(hb)) * LSC);
    h = __half_as_ushort(hb);
    l = __half_as_ushort(lb);
}

// output transform rows A^T = {{1,1,1,0},{0,1,-1,-1}}
__device__ const float cA0[4] = {1.f, 1.f, 1.f, 0.f};
__device__ const float cA1[4] = {0.f, 1.f, -1.f, -1.f};

// ---------- prep: per-Cout 1/(||k||^2 + eps) ----------
__global__ void prep_norm(const float* __restrict__ kern) {
    __shared__ float red[512];
    int t = threadIdx.x;
    int co = t & 127;
    int part = t >> 7;
    float s = 0.f;
#pragma unroll 4
    for (int i = part * 144; i < part * 144 + 144; i++) {
        float v = kern[i * COUT + co];
        s += v * v;
    }
    red[t] = s;
    __syncthreads();
    if (t < 128)
        g_inv_norm[co] = 1.f / (red[co] + red[co + 128] + red[co + 256] + red[co + 384] + EPSV);
}

// ---------- prep: weight transform W~ = G g G^T, fp16 hi/lo ----------
__global__ void prep_Wt(const float* __restrict__ kern) {
    int id = blockIdx.x * 256 + threadIdx.x;   // 8192
    int co = id & 127;
    int ci = id >> 7;

    float g[3][3];
#pragma unroll
    for (int kh = 0; kh < 3; kh++)
#pragma unroll
        for (int kw = 0; kw < 3; kw++)
            g[kh][kw] = kern[(kh * 3 + kw) * (CIN * COUT) + ci * COUT + co];

    float t[4][3];
#pragma unroll
    for (int kw = 0; kw < 3; kw++) {
        t[0][kw] = g[0][kw];
        t[1][kw] = 0.5f * (g[0][kw] + g[1][kw] + g[2][kw]);
        t[2][kw] = 0.5f * (g[0][kw] - g[1][kw] + g[2][kw]);
        t[3][kw] = g[2][kw];
    }
#pragma unroll
    for (int i = 0; i < 4; i++) {
        float wv[4];
        wv[0] = t[i][0];
        wv[1] = 0.5f * (t[i][0] + t[i][1] + t[i][2]);
        wv[2] = 0.5f * (t[i][0] - t[i][1] + t[i][2]);
        wv[3] = t[i][2];
#pragma unroll
        for (int j = 0; j < 4; j++) {
            int p = i * 4 + j;
            uint16_t h, l;
            hsplit(wv[j], h, l);
            g_Wh[p][ci][co] = __ushort_as_half(h);
            g_Wl[p][ci][co] = __ushort_as_half(l);
        }
    }
}

// ---------- prep: input transform X~ = B^T d B, smem-staged ----------
#define XSP 66
#define XT_SMEM (4 * 64 * XSP * 4)
__global__ __launch_bounds__(256)
void prep_Xt(const float* __restrict__ x) {
    extern __shared__ float xs[];
    const int n = blockIdx.x >> 5;
    const int ty = blockIdx.x & 31;
    const int tid = threadIdx.x;
    const int w = tid >> 5;           // warp: 4 tx tiles
    const int l = tid & 31;           // ci pair

#pragma unroll
    for (int i = 0; i < 64; i++) {
        int idx = tid + i * 256;      // 16384 = 64ci * 4r * 64c
        int ci = idx >> 8;
        int rem = idx & 255;
        int r = rem >> 6;
        int c = rem & 63;
        int gr = 2 * ty - 1 + r;
        float v = (gr >= 0 && gr < HDIM)
                      ? __ldg(x + ((n * CIN + ci) * HDIM + gr) * WDIM + c)
                      : 0.f;
        xs[(r * 64 + c) * XSP + ci] = v;
    }
    __syncthreads();

#pragma unroll 1
    for (int t = 0; t < 4; t++) {
        const int tx = w * 4 + t;
        const int tile = n * 1024 + ty * 32 + tx;
        const int wb = 2 * tx - 1;

        float2 d2[4][4];
#pragma unroll
        for (int c = 0; c < 4; c++) {
            int gc = wb + c;
            bool ok = (gc >= 0) & (gc < WDIM);
#pragma unroll
            for (int r = 0; r < 4; r++) {
                d2[r][c] = ok ? *(const float2*)&xs[(r * 64 + gc) * XSP + 2 * l]
                              : make_float2(0.f, 0.f);
            }
        }

        uint32_t hv[16], lv[16];
#pragma unroll
        for (int cc = 0; cc < 2; cc++) {
            float d[4][4];
#pragma unroll
            for (int r = 0; r < 4; r++)
#pragma unroll
                for (int c = 0; c < 4; c++)
                    d[r][c] = cc ? d2[r][c].y : d2[r][c].x;

            float s[4][4];
#pragma unroll
            for (int c = 0; c < 4; c++) {
                s[0][c] = d[0][c] - d[2][c];
                s[1][c] = d[1][c] + d[2][c];
                s[2][c] = d[2][c] - d[1][c];
                s[3][c] = d[1][c] - d[3][c];
            }
#pragma unroll
            for (int i = 0; i < 4; i++) {
                float vv[4];
                vv[0] = s[i][0] - s[i][2];
                vv[1] = s[i][1] + s[i][2];
                vv[2] = s[i][2] - s[i][1];
                vv[3] = s[i][1] - s[i][3];
#pragma unroll
                for (int j = 0; j < 4; j++) {
                    int p = i * 4 + j;
                    uint16_t h, lo;
                    hsplit(vv[j], h, lo);
                    if (cc == 0) {
                        hv[p] = (uint32_t)h;
                        lv[p] = (uint32_t)lo;
                    } else {
                        hv[p] |= (uint32_t)h << 16;
                        lv[p] |= (uint32_t)lo << 16;
                    }
                }
            }
        }
#pragma unroll
        for (int p = 0; p < 16; p++) {
            ((uint32_t*)g_Xh[p][tile])[l] = hv[p];
            ((uint32_t*)g_Xl[p][tile])[l] = lv[p];
        }
    }
}

// ---------- main: HMMA fp16x3 Winograd GEMM, 512-thr CTA = 64 tiles x 128 co ----
// smem per buffer: Ah +0 (64x144B), Al +9216, Bh +18432 (64x272B), Bl +35840
//   BUFSZ = 18432 + 34816 = 53248; x2 buffers; norm/bias after.
#define A_PL   9216
#define B_PL   17408
#define BUF_B  18432
#define BUFSZ  53248
#define NORMF  (2 * BUFSZ / 4)          // float index 26624
#define BIASF  (NORMF + 128)
#define SMEM_BYTES (2 * BUFSZ + 1024)

__global__ __launch_bounds__(512, 1)
void wino_gemm(const float* __restrict__ mem, const float* __restrict__ beta_p,
               const float* __restrict__ b_p, float* __restrict__ out) {
    extern __shared__ char smc[];
    float* smf = (float*)smc;
    const uint32_t smu = (uint32_t)__cvta_generic_to_shared(smc);

    const int tid = threadIdx.x;
    const int lane = tid & 31;
    const int wrp = tid >> 5;
    const int mw = wrp & 3;           // M-warp: tiles mw*16..+15
    const int nw = wrp >> 2;          // N-warp: co nw*32..+31
    const int TB = blockIdx.x * 64;   // base tile

    if (tid < 128) {
        smf[NORMF + tid] = g_inv_norm[tid];
        smf[BIASF + tid] = b_p[tid];
    }

#define STAGE(p, buf)                                                         \
    {                                                                         \
        const int pp = (p);                                                   \
        uint32_t base = smu + (buf)*BUFSZ;                                    \
        _Pragma("unroll")                                                     \
        for (int i = 0; i < 2; i++) {  /* A: 1024 chunks (2 planes x 64 x 8) */ \
            int idx = tid + i * 512;                                          \
            int pl = idx >> 9;                                                \
            int q = idx & 511;                                                \
            int row = q >> 3, c = q & 7;                                      \
            cpa16(base + pl * A_PL + row * 144 + c * 16,                      \
                  (pl ? g_Xl[pp][TB + row] : g_Xh[pp][TB + row]) + c * 8);    \
        }                                                                     \
        _Pragma("unroll")                                                     \
        for (int i = 0; i < 4; i++) {  /* B: 2048 chunks (2 planes x 64 x 16) */ \
            int idx = tid + i * 512;                                          \
            int pl = idx >> 10;                                               \
            int q = idx & 1023;                                               \
            int row = q >> 4, c = q & 15;                                     \
            cpa16(base + BUF_B + pl * B_PL + row * 272 + c * 16,              \
                  (pl ? g_Wl[pp][row] : g_Wh[pp][row]) + c * 8);              \
        }                                                                     \
    }

    float acc[4][16];
#pragma unroll
    for (int q = 0; q < 4; q++)
#pragma unroll
        for (int i = 0; i < 16; i++) acc[q][i] = 0.f;

    // ldmatrix address offsets
    const uint32_t arow_off =
        (uint32_t)(mw * 16 + (lane & 15)) * 144 + (uint32_t)((lane >> 4) * 8) * 2;
    const uint32_t brow_off =
        (uint32_t)(lane & 15) * 272 + (uint32_t)(nw * 32 + (lane >> 4) * 8) * 2;

    STAGE(0, 0);
    cpcommit();

#pragma unroll 1
    for (int p = 0; p < 16; p++) {
        const int buf = p & 1;
        cpwait<0>();
        __syncthreads();
        if (p < 15) {
            STAGE(p + 1, buf ^ 1);
            cpcommit();
        }

        const uint32_t Ab = smu + buf * BUFSZ;
        float mh[4][4], ml[4][4];
#pragma unroll
        for (int nb = 0; nb < 4; nb++)
#pragma unroll
            for (int k = 0; k < 4; k++) { mh[nb][k] = 0.f; ml[nb][k] = 0.f; }

#pragma unroll
        for (int kb = 0; kb < 4; kb++) {
            uint32_t aAddr = Ab + arow_off + kb * 32;
            uint32_t bAddr = Ab + BUF_B + (uint32_t)(kb * 16) * 272 + brow_off;
            uint32_t ah[4], al[4];
            uint32_t bh0[4], bh1[4], bl0[4], bl1[4];
            ldsm_x4(ah[0], ah[1], ah[2], ah[3], aAddr);
            ldsm_x4(al[0], al[1], al[2], al[3], aAddr + A_PL);
            ldsm_x4t(bh0[0], bh0[1], bh0[2], bh0[3], bAddr);        // n 0..15
            ldsm_x4t(bh1[0], bh1[1], bh1[2], bh1[3], bAddr + 32);   // n 16..31
            ldsm_x4t(bl0[0], bl0[1], bl0[2], bl0[3], bAddr + B_PL);
            ldsm_x4t(bl1[0], bl1[1], bl1[2], bl1[3], bAddr + B_PL + 32);
            // hi*hi
            mma16(mh[0], ah, bh0[0], bh0[1]);
            mma16(mh[1], ah, bh0[2], bh0[3]);
            mma16(mh[2], ah, bh1[0], bh1[1]);
            mma16(mh[3], ah, bh1[2], bh1[3]);
            // hi*lo
            mma16(ml[0], ah, bl0[0], bl0[1]);
            mma16(ml[1], ah, bl0[2], bl0[3]);
            mma16(ml[2], ah, bl1[0], bl1[1]);
            mma16(ml[3], ah, bl1[2], bl1[3]);
            // lo*hi
            mma16(ml[0], al, bh0[0], bh0[1]);
            mma16(ml[1], al, bh0[2], bh0[3]);
            mma16(ml[2], al, bh1[0], bh1[1]);
            mma16(ml[3], al, bh1[2], bh1[3]);
        }

        // fold: acc[pyx] += AT[py][fi]*AT[px][fj] * (mh + ml*2^-11)
        const int fi = p >> 2, fj = p & 3;
        const float a0i = cA0[fi], a1i = cA1[fi];
        const float a0j = cA0[fj], a1j = cA1[fj];
        float dq[4] = {a0i * a0j, a0i * a1j, a1i * a0j, a1i * a1j};
#pragma unroll
        for (int nb = 0; nb < 4; nb++)
#pragma unroll
            for (int k = 0; k < 4; k++) {
                float mm = fmaf(ml[nb][k], ILSC, mh[nb][k]);
#pragma unroll
                for (int q = 0; q < 4; q++) acc[q][nb * 4 + k] += dq[q] * mm;
            }
    }

    // ---- fused epilogue: LIF membrane + multi-threshold spike ----
    const float beta = *beta_p;
    const float omb = 1.f - beta;

#pragma unroll
    for (int nb = 0; nb < 4; nb++) {
#pragma unroll
        for (int cs = 0; cs < 2; cs++) {
            const int co = nw * 32 + nb * 8 + 2 * (lane & 3) + cs;
            const float invn = smf[NORMF + co];
            const float bb = smf[BIASF + co];
#pragma unroll
            for (int rs = 0; rs < 2; rs++) {
                const int t = TB + mw * 16 + (lane >> 2) + rs * 8;
                const int n = t >> 10;
                const int tyy = (t >> 5) & 31;
                const int txx = t & 31;
                const int mi = nb * 4 + rs * 2 + cs;
                const int base0 = ((n * COUT + co) * HDIM + 2 * tyy) * WDIM + 2 * txx;
#pragma unroll
                for (int py = 0; py < 2; py++) {
                    const int idx = base0 + py * WDIM;
                    float2 mv = *(const float2*)(mem + idx);
                    float c0 = acc[py * 2 + 0][mi];
                    float c1 = acc[py * 2 + 1][mi];
                    float nm0 = mv.x * beta + c0 * omb;
                    float nm1 = mv.y * beta + c1 * omb;
                    float mt0 = nm0 * invn - bb;
                    float mt1 = nm1 * invn - bb;
                    float s0 = (float)((mt0 > 0.f) + (mt0 > 1.f) + (mt0 > 2.f) + (mt0 > 3.f));
                    float s1 = (float)((mt1 > 0.f) + (mt1 > 1.f) + (mt1 > 2.f) + (mt1 > 3.f));
                    float f0 = (s0 > 0.f) ? 0.f : nm0;
                    float f1 = (s1 > 0.f) ? 0.f : nm1;
                    *(float2*)(out + idx) = make_float2(s0, s1);
                    *(float2*)(out + FM_OFF + idx) = make_float2(f0, f1);
                }
            }
        }
    }
}

extern "C" void kernel_launch(void* const* d_in, const int* in_sizes, int n_in,
                              void* d_out, int out_size) {
    const float* x    = (const float*)d_in[0];
    const float* mem  = (const float*)d_in[1];
    const float* kern = (const float*)d_in[2];
    const float* beta = (const float*)d_in[3];
    const float* b    = (const float*)d_in[4];
    float* out = (float*)d_out;

    cudaFuncSetAttribute(wino_gemm, cudaFuncAttributeMaxDynamicSharedMemorySize,
                         SMEM_BYTES);
    cudaFuncSetAttribute(prep_Xt, cudaFuncAttributeMaxDynamicSharedMemorySize,
                         XT_SMEM);

    prep_norm<<<1, 512>>>(kern);
    prep_Wt<<<32, 256>>>(kern);
    prep_Xt<<<1024, 256, XT_SMEM>>>(x);
    wino_gemm<<<NTILES / 64, 512, SMEM_BYTES>>>(mem, beta, b, out);
}